// round 8
// baseline (speedup 1.0000x reference)
#include <cuda_runtime.h>
#include <cuda_bf16.h>
#include <cstdint>

// Problem dims (fixed)
#define BATCH 256
#define TSEQ  512
#define DDIM  128
#define ND3   384   // 3*D
#define NC    768   // combined output cols (Wa | Wb)
#define TD    65536 // TSEQ*DDIM (one sample of states)

// ---------------- scratch (static device arrays; no allocations) ----------------
__device__ float g_xpc[(size_t)BATCH * TSEQ * NC];  // [b][tau][768] natural-order proj
__device__ float g_g[(size_t)BATCH * TSEQ * DDIM];  // GRU a states [b][t][d]
__device__ float g_h[(size_t)BATCH * TSEQ * DDIM];  // GRU b states [b][t][d]
__device__ int   g_perm[BATCH];                     // descending-length permutation

typedef unsigned long long ull;

__device__ __forceinline__ void ffma2(ull &d, ull a, ull b) {
    asm("fma.rn.f32x2 %0, %1, %2, %0;" : "+l"(d) : "l"(a), "l"(b));
}
__device__ __forceinline__ ull pk2(float lo, float hi) {
    ull r; asm("mov.b64 %0, {%1,%2};" : "=l"(r) : "f"(lo), "f"(hi)); return r;
}
__device__ __forceinline__ float2 upk2(ull v) {
    float lo, hi; asm("mov.b64 {%0,%1}, %2;" : "=f"(lo), "=f"(hi) : "l"(v));
    return make_float2(lo, hi);
}
__device__ __forceinline__ float sigm(float v) { return 1.f / (1.f + __expf(-v)); }

// ============================================================================
// Kernel 0: descending rank-sort of lengths -> g_perm; also zero d_out
// (it is poisoned 0xAA and k_attn accumulates via atomicAdd).
// ============================================================================
__global__ void __launch_bounds__(BATCH) k_sort(const int* __restrict__ lengths,
                                                float* __restrict__ out)
{
    __shared__ int ls[BATCH];
    const int i = threadIdx.x;
    ls[i] = lengths[i];
    for (int idx = i; idx < BATCH * DDIM; idx += BATCH) out[idx] = 0.f;
    __syncthreads();
    const int li = ls[i];
    int r = 0;
#pragma unroll 8
    for (int j = 0; j < BATCH; ++j) {
        int lj = ls[j];
        r += (lj > li) || (lj == li && j < i);
    }
    g_perm[r] = i;
}

// ============================================================================
// Kernel 1: natural-order projection  g_xpc[b][tau][c] = x[b][tau] @ (Wa|Wb) + bias
// (unchanged from R7 — behaved per model)
// ============================================================================
__global__ void __launch_bounds__(256) k_xp(
    const float* __restrict__ x, const int* __restrict__ lengths,
    const float* __restrict__ Wa, const float* __restrict__ ba,
    const float* __restrict__ Wb, const float* __restrict__ bb)
{
    const int rt   = blockIdx.x;
    const int b    = rt >> 3;
    const int tau0 = (rt & 7) << 6;
    const int len  = lengths[b];
    if (tau0 >= len) return;            // dead tile

    __shared__ __align__(16) float2 As2[32][66];
    __shared__ __align__(16) float2 Bs2[32][66];

    const int c0 = blockIdx.y << 6;
    const float* W    = (c0 < ND3) ? Wa : Wb;
    const float* bias = (c0 < ND3) ? ba : bb;
    const int cw = (c0 < ND3) ? c0 : (c0 - ND3);

    const int tid  = threadIdx.x;
    const int w    = tid >> 5, lane = tid & 31;
    const int txp  = ((w & 1) << 3) + (lane & 7);
    const int typ  = ((w >> 1) << 2) + (lane >> 3);

    ull acc[4][4];
#pragma unroll
    for (int i = 0; i < 4; i++)
#pragma unroll
        for (int j = 0; j < 4; j++) acc[i][j] = 0ull;

    for (int kc = 0; kc < 2; ++kc) {
        __syncthreads();
#pragma unroll
        for (int l = 0; l < 16; ++l) {
            int idx = tid + l * 256;
            int tt = idx >> 6, kk = idx & 63;
            float v = x[((size_t)b * TSEQ + tau0 + tt) * DDIM + kc * 64 + kk];
            ((float*)&As2[kk >> 1][tt])[kk & 1] = v;
        }
#pragma unroll
        for (int l = 0; l < 16; ++l) {
            int idx = tid + l * 256;
            int kk = idx >> 6, jj = idx & 63;
            float wv = W[(size_t)(kc * 64 + kk) * ND3 + cw + jj];
            ((float*)&Bs2[kk >> 1][jj])[kk & 1] = wv;
        }
        __syncthreads();
#pragma unroll
        for (int q = 0; q < 32; ++q) {
            ulonglong2 a0 = *(const ulonglong2*)&As2[q][4 * typ];
            ulonglong2 a1 = *(const ulonglong2*)&As2[q][4 * typ + 2];
            ulonglong2 b0 = *(const ulonglong2*)&Bs2[q][4 * txp];
            ulonglong2 b1 = *(const ulonglong2*)&Bs2[q][4 * txp + 2];
            ull av[4] = { a0.x, a0.y, a1.x, a1.y };
            ull bv[4] = { b0.x, b0.y, b1.x, b1.y };
#pragma unroll
            for (int i = 0; i < 4; i++)
#pragma unroll
                for (int j = 0; j < 4; j++)
                    ffma2(acc[i][j], av[i], bv[j]);
        }
    }
#pragma unroll
    for (int i = 0; i < 4; i++) {
        int tau = tau0 + 4 * typ + i;
        float4 o;
        float* po = (float*)&o;
#pragma unroll
        for (int j = 0; j < 4; j++) {
            float2 f = upk2(acc[i][j]);
            po[j] = f.x + f.y + bias[cw + 4 * txp + j];
        }
        *(float4*)&g_xpc[((size_t)b * TSEQ + tau) * NC + c0 + 4 * txp] = o;
    }
}

// ============================================================================
// Kernel 2: masked GRU recurrence, K-split over 2 thread groups (768 threads)
// to keep per-thread U at 64 registers (no spill of the hot array).
// 148 persistent blocks = 2 GRUs x 74 snake slots; slot s runs sorted pair s
// then pair 147-s. Partial dot products combined via smem; gates on warps 0-7.
// ============================================================================
__global__ void __launch_bounds__(768, 1) k_gru(
    const int*   __restrict__ lengths,
    const float* __restrict__ Ua, const float* __restrict__ ba_rec,
    const float* __restrict__ Ub, const float* __restrict__ bb_rec)
{
    __shared__ __align__(16) float hsm[2][DDIM];
    __shared__ float part[2][2][ND3];   // [kgroup][sample][col]

    const int gru  = (blockIdx.x >= 74) ? 1 : 0;
    const int slot = blockIdx.x - gru * 74;
    const int tid  = threadIdx.x;
    const int g    = (tid >= 384) ? 1 : 0;   // k-half
    const int j    = tid - g * 384;          // column

    const float* U   = gru ? Ub     : Ua;
    const float* brp = gru ? bb_rec : ba_rec;
    float*       st  = gru ? g_h    : g_g;
    const int    coff = gru * ND3;

    // thread's 32 k-pairs: kp in [32g, 32g+32)
    ull u2[32];
#pragma unroll
    for (int i = 0; i < 32; ++i) {
        int k0 = 64 * g + 2 * i;
        u2[i] = pk2(U[(size_t)k0 * ND3 + j], U[(size_t)(k0 + 1) * ND3 + j]);
    }
    const ull binit = (g == 0) ? pk2(brp[j], 0.f) : 0ull;

    const int s = (tid >> 7) & 1;     // gate sample (tid<256 only)
    const int d = tid & 127;

    for (int pi = 0; pi < 2; ++pi) {
        const int pr = pi ? (147 - slot) : slot;
        if (pr >= 128) continue;      // slots 0..19 have no snake partner

        const int b_s0 = g_perm[2 * pr];
        const int b_s1 = g_perm[2 * pr + 1];
        const int len0 = lengths[b_s0];
        const int len1 = lengths[b_s1];
        const int maxlen = max(len0, len1);
        const int b_g   = s ? b_s1 : b_s0;
        const int len_g = s ? len1 : len0;

        // gate-thread streaming pointers
        const float* xptr = g_xpc + ((size_t)b_g * TSEQ + (len_g - 1)) * NC + coff + d;
        float*       stp  = st + (size_t)b_g * TD + d;

        for (int idx = tid; idx < 2 * DDIM; idx += 768) ((float*)hsm)[idx] = 0.f;
        __syncthreads();

        const float* h0p = &hsm[0][g * 64];
        const float* h1p = &hsm[1][g * 64];

        for (int t = 0; t < maxlen; ++t) {
            // prefetch gate inputs (warps 0-7)
            float xz = 0.f, xr = 0.f, xh = 0.f;
            if (tid < 256 && t < len_g) {
                xz = xptr[0];
                xr = xptr[128];
                xh = xptr[256];
            }
            // partial rp over this thread's k-half, both samples, 2 chains
            ull acc0 = binit, acc1 = binit;
#pragma unroll
            for (int q = 0; q < 16; ++q) {
                ulonglong2 ha = *(const ulonglong2*)&h0p[4 * q];
                ulonglong2 hb = *(const ulonglong2*)&h1p[4 * q];
                ffma2(acc0, u2[2 * q],     ha.x);
                ffma2(acc1, u2[2 * q],     hb.x);
                ffma2(acc0, u2[2 * q + 1], ha.y);
                ffma2(acc1, u2[2 * q + 1], hb.y);
            }
            { float2 f = upk2(acc0); part[g][0][j] = f.x + f.y; }
            { float2 f = upk2(acc1); part[g][1][j] = f.x + f.y; }
            __syncthreads();

            if (tid < 256) {
                float h_old = hsm[s][d];
                float hn = h_old;
                if (t < len_g) {
                    float rpz = part[0][s][d]       + part[1][s][d];
                    float rpr = part[0][s][128 + d] + part[1][s][128 + d];
                    float rph = part[0][s][256 + d] + part[1][s][256 + d];
                    float zg = sigm(xz + rpz);
                    float rg = sigm(xr + rpr);
                    float hh = tanhf(xh + rg * rph);
                    hn = zg * h_old + (1.f - zg) * hh;
                }
                hsm[s][d] = hn;
                stp[0] = hn;
            }
            __syncthreads();
            xptr -= NC;
            stp  += DDIM;
        }
        // tail fill: t in [maxlen, T) carries the final state
        const int tail = TSEQ - maxlen;
        for (int idx = tid; idx < tail * 256; idx += 768) {
            int dd = idx & 127;
            int ss = (idx >> 7) & 1;
            int tt = idx >> 8;
            int bb = ss ? b_s1 : b_s0;
            st[(size_t)bb * TD + (size_t)(maxlen + tt) * DDIM + dd] = hsm[ss][dd];
        }
        __syncthreads();
    }
}

// ============================================================================
// Kernel 3: fused attention epilogue. TWO blocks per sample (time split),
// 128 threads each; softmax computed redundantly (identical fp result);
// halves combined by atomicAdd (2 commutative adds -> deterministic).
// ============================================================================
__global__ void __launch_bounds__(128, 2) k_attn(
    const float* __restrict__ x,
    const float* __restrict__ W_alpha, const float* __restrict__ b_alpha,
    const float* __restrict__ W_beta,  const float* __restrict__ b_beta,
    float* __restrict__ out)
{
    __shared__ float e_s[TSEQ];
    __shared__ float red[4];
    __shared__ float scal[2];
    __shared__ __align__(16) float hwin[8][DDIM];
    __shared__ float xwin[8][DDIM];

    const int b    = blockIdx.x >> 1;
    const int half = blockIdx.x & 1;
    const int tid  = threadIdx.x;
    const int lane = tid & 31, w = tid >> 5;

    // ---- phase 1: e[t] = g[b][t] . W_alpha + b_alpha (warp per t) ----
    float4 wa = *(const float4*)&W_alpha[lane * 4];
    const float b_a = b_alpha[0];
    const float* gbase = g_g + (size_t)b * TD;
    for (int tt = 0; tt < 128; ++tt) {
        int t = tt * 4 + w;
        float4 gv = *(const float4*)&gbase[(size_t)t * DDIM + lane * 4];
        float sum = gv.x * wa.x + gv.y * wa.y + gv.z * wa.z + gv.w * wa.w;
#pragma unroll
        for (int o = 16; o > 0; o >>= 1) sum += __shfl_xor_sync(0xffffffffu, sum, o);
        if (lane == 0) e_s[t] = sum + b_a;
    }
    __syncthreads();

    // ---- softmax over t (unnormalized exp; divide once at the end) ----
    float m = -1e30f;
    for (int i = tid; i < TSEQ; i += 128) m = fmaxf(m, e_s[i]);
#pragma unroll
    for (int o = 16; o > 0; o >>= 1) m = fmaxf(m, __shfl_xor_sync(0xffffffffu, m, o));
    if (lane == 0) red[w] = m;
    __syncthreads();
    if (tid == 0) scal[0] = fmaxf(fmaxf(red[0], red[1]), fmaxf(red[2], red[3]));
    __syncthreads();
    const float M = scal[0];
    float ss = 0.f;
    for (int i = tid; i < TSEQ; i += 128) { float p = __expf(e_s[i] - M); e_s[i] = p; ss += p; }
#pragma unroll
    for (int o = 16; o > 0; o >>= 1) ss += __shfl_xor_sync(0xffffffffu, ss, o);
    if (lane == 0) red[w] = ss;
    __syncthreads();
    if (tid == 0) scal[1] = red[0] + red[1] + red[2] + red[3];
    __syncthreads();
    const float Sinv = 1.f / scal[1];

    // ---- phase 2: beta GEMV over this block's half of the time axis ----
    ull wb2[64];
#pragma unroll
    for (int kp = 0; kp < 64; ++kp)
        wb2[kp] = pk2(W_beta[(size_t)(2 * kp) * DDIM + tid],
                      W_beta[(size_t)(2 * kp + 1) * DDIM + tid]);
    const float bbv = b_beta[tid];
    const int tws = half * 256;
    const float* hbase = g_h + (size_t)b * TD;
    const float* xbase = x   + (size_t)b * TD;
    float acc = 0.f;

    for (int tw = 0; tw < 256; tw += 8) {
        __syncthreads();
#pragma unroll
        for (int l = 0; l < 8; ++l) {
            int idx = tid + l * 128;
            int tt = idx >> 7, k = idx & 127;
            hwin[tt][k] = hbase[(size_t)(tws + tw + tt) * DDIM + k];
            xwin[tt][k] = xbase[(size_t)(tws + tw + tt) * DDIM + k];
        }
        __syncthreads();
#pragma unroll
        for (int tt = 0; tt < 8; ++tt) {
            // two interleaved FFMA2 chains (break the 64-deep latency chain)
            ull a2a = 0ull, a2b = 0ull;
#pragma unroll
            for (int q = 0; q < 32; q += 2) {
                ulonglong2 hva = *(const ulonglong2*)&hwin[tt][4 * q];
                ulonglong2 hvb = *(const ulonglong2*)&hwin[tt][4 * q + 4];
                ffma2(a2a, wb2[2 * q],     hva.x);
                ffma2(a2b, wb2[2 * q + 2], hvb.x);
                ffma2(a2a, wb2[2 * q + 1], hva.y);
                ffma2(a2b, wb2[2 * q + 3], hvb.y);
            }
            float2 fa = upk2(a2a);
            float2 fb = upk2(a2b);
            float beta = tanhf(fa.x + fa.y + fb.x + fb.y + bbv);
            acc += e_s[tws + tw + tt] * beta * xwin[tt][tid];
        }
    }
    atomicAdd(&out[(size_t)b * DDIM + tid], acc * Sinv);
}

// ============================================================================
extern "C" void kernel_launch(void* const* d_in, const int* in_sizes, int n_in,
                              void* d_out, int out_size)
{
    const float* x       = (const float*)d_in[0];
    const int*   lengths = (const int*)  d_in[1];
    const float* Wa      = (const float*)d_in[2];
    const float* Ua      = (const float*)d_in[3];
    const float* ba_in   = (const float*)d_in[4];
    const float* ba_rec  = (const float*)d_in[5];
    const float* Wb      = (const float*)d_in[6];
    const float* Ub      = (const float*)d_in[7];
    const float* bb_in   = (const float*)d_in[8];
    const float* bb_rec  = (const float*)d_in[9];
    const float* W_alpha = (const float*)d_in[10];
    const float* b_alpha = (const float*)d_in[11];
    const float* W_beta  = (const float*)d_in[12];
    const float* b_beta  = (const float*)d_in[13];
    float* out = (float*)d_out;

    k_sort<<<1, BATCH>>>(lengths, out);
    k_xp  <<<dim3(2048, 12), 256>>>(x, lengths, Wa, ba_in, Wb, bb_in);
    k_gru <<<148, 768>>>(lengths, Ua, ba_rec, Ub, bb_rec);
    k_attn<<<512, 128>>>(x, W_alpha, b_alpha, W_beta, b_beta, out);
    (void)in_sizes; (void)n_in; (void)out_size;
}

// round 9
// speedup vs baseline: 1.1859x; 1.1859x over previous
#include <cuda_runtime.h>
#include <cuda_bf16.h>
#include <cstdint>

// Problem dims (fixed)
#define BATCH 256
#define TSEQ  512
#define DDIM  128
#define ND3   384   // 3*D
#define NC    768   // combined output cols (Wa | Wb)
#define TD    65536 // TSEQ*DDIM (one sample of states)

// ---------------- scratch (static device arrays; no allocations) ----------------
__device__ float g_xpc[(size_t)BATCH * TSEQ * NC];  // [b][tau][768] natural-order proj
__device__ float g_g[(size_t)BATCH * TSEQ * DDIM];  // GRU a states [b][t][d]
__device__ float g_h[(size_t)BATCH * TSEQ * DDIM];  // GRU b states [b][t][d]
__device__ int   g_perm[BATCH];                     // descending-length permutation

typedef unsigned long long ull;

__device__ __forceinline__ void ffma2(ull &d, ull a, ull b) {
    asm("fma.rn.f32x2 %0, %1, %2, %0;" : "+l"(d) : "l"(a), "l"(b));
}
__device__ __forceinline__ ull pk2(float lo, float hi) {
    ull r; asm("mov.b64 %0, {%1,%2};" : "=l"(r) : "f"(lo), "f"(hi)); return r;
}
__device__ __forceinline__ float2 upk2(ull v) {
    float lo, hi; asm("mov.b64 {%0,%1}, %2;" : "=f"(lo), "=f"(hi) : "l"(v));
    return make_float2(lo, hi);
}
__device__ __forceinline__ float sigm(float v) { return 1.f / (1.f + __expf(-v)); }
// tanh via exp: 1 MUFU + few ops, abs err ~1e-7 (vs ~40-instr libm tanhf)
__device__ __forceinline__ float ftanh(float y) {
    float e = __expf(2.f * y);
    return 1.f - 2.f / (e + 1.f);
}
__device__ __forceinline__ unsigned sptr(const void* p) {
    return (unsigned)__cvta_generic_to_shared(p);
}
__device__ __forceinline__ void cp8(unsigned dst, const void* src) {
    asm volatile("cp.async.ca.shared.global [%0], [%1], 8;" :: "r"(dst), "l"(src));
}
#define CP_COMMIT() asm volatile("cp.async.commit_group;")
#define CP_WAIT1()  asm volatile("cp.async.wait_group 1;")
#define CP_WAIT0()  asm volatile("cp.async.wait_group 0;")

// ============================================================================
// Kernel 0: descending rank-sort of lengths -> g_perm (O(B^2), one block)
// ============================================================================
__global__ void __launch_bounds__(BATCH) k_sort(const int* __restrict__ lengths)
{
    __shared__ int ls[BATCH];
    const int i = threadIdx.x;
    ls[i] = lengths[i];
    __syncthreads();
    const int li = ls[i];
    int r = 0;
#pragma unroll 8
    for (int j = 0; j < BATCH; ++j) {
        int lj = ls[j];
        r += (lj > li) || (lj == li && j < i);
    }
    g_perm[r] = i;
}

// ============================================================================
// Kernel 1: natural-order projection  g_xpc[b][tau][c] = x[b][tau] @ (Wa|Wb) + bias
// (unchanged — behaved per model)
// ============================================================================
__global__ void __launch_bounds__(256) k_xp(
    const float* __restrict__ x, const int* __restrict__ lengths,
    const float* __restrict__ Wa, const float* __restrict__ ba,
    const float* __restrict__ Wb, const float* __restrict__ bb)
{
    const int rt   = blockIdx.x;
    const int b    = rt >> 3;
    const int tau0 = (rt & 7) << 6;
    const int len  = lengths[b];
    if (tau0 >= len) return;            // dead tile

    __shared__ __align__(16) float2 As2[32][66];
    __shared__ __align__(16) float2 Bs2[32][66];

    const int c0 = blockIdx.y << 6;
    const float* W    = (c0 < ND3) ? Wa : Wb;
    const float* bias = (c0 < ND3) ? ba : bb;
    const int cw = (c0 < ND3) ? c0 : (c0 - ND3);

    const int tid  = threadIdx.x;
    const int w    = tid >> 5, lane = tid & 31;
    const int txp  = ((w & 1) << 3) + (lane & 7);
    const int typ  = ((w >> 1) << 2) + (lane >> 3);

    ull acc[4][4];
#pragma unroll
    for (int i = 0; i < 4; i++)
#pragma unroll
        for (int j = 0; j < 4; j++) acc[i][j] = 0ull;

    for (int kc = 0; kc < 2; ++kc) {
        __syncthreads();
#pragma unroll
        for (int l = 0; l < 16; ++l) {
            int idx = tid + l * 256;
            int tt = idx >> 6, kk = idx & 63;
            float v = x[((size_t)b * TSEQ + tau0 + tt) * DDIM + kc * 64 + kk];
            ((float*)&As2[kk >> 1][tt])[kk & 1] = v;
        }
#pragma unroll
        for (int l = 0; l < 16; ++l) {
            int idx = tid + l * 256;
            int kk = idx >> 6, jj = idx & 63;
            float wv = W[(size_t)(kc * 64 + kk) * ND3 + cw + jj];
            ((float*)&Bs2[kk >> 1][jj])[kk & 1] = wv;
        }
        __syncthreads();
#pragma unroll
        for (int q = 0; q < 32; ++q) {
            ulonglong2 a0 = *(const ulonglong2*)&As2[q][4 * typ];
            ulonglong2 a1 = *(const ulonglong2*)&As2[q][4 * typ + 2];
            ulonglong2 b0 = *(const ulonglong2*)&Bs2[q][4 * txp];
            ulonglong2 b1 = *(const ulonglong2*)&Bs2[q][4 * txp + 2];
            ull av[4] = { a0.x, a0.y, a1.x, a1.y };
            ull bv[4] = { b0.x, b0.y, b1.x, b1.y };
#pragma unroll
            for (int i = 0; i < 4; i++)
#pragma unroll
                for (int j = 0; j < 4; j++)
                    ffma2(acc[i][j], av[i], bv[j]);
        }
    }
#pragma unroll
    for (int i = 0; i < 4; i++) {
        int tau = tau0 + 4 * typ + i;
        float4 o;
        float* po = (float*)&o;
#pragma unroll
        for (int j = 0; j < 4; j++) {
            float2 f = upk2(acc[i][j]);
            po[j] = f.x + f.y + bias[cw + 4 * txp + j];
        }
        *(float4*)&g_xpc[((size_t)b * TSEQ + tau) * NC + c0 + 4 * txp] = o;
    }
}

// ============================================================================
// Kernel 2: masked GRU recurrence (R7 base: 384 thr, 2 samples, snake slots)
// + cp.async double-buffered xp prefetch by warps 8-11 (zero reg cost)
// + exp-based tanh on the gate critical path.
// ============================================================================
__global__ void __launch_bounds__(384, 1) k_gru(
    const int*   __restrict__ lengths,
    const float* __restrict__ Ua, const float* __restrict__ ba_rec,
    const float* __restrict__ Ub, const float* __restrict__ bb_rec)
{
    __shared__ __align__(16) float hsm[2][DDIM];
    __shared__ float rps[2][ND3];
    __shared__ __align__(16) float xsm[2][2 * ND3];   // [buf][s*384 + c]

    const int gru  = (blockIdx.x >= 74) ? 1 : 0;
    const int slot = blockIdx.x - gru * 74;
    const int j    = threadIdx.x;

    const float* U   = gru ? Ub     : Ua;
    const float* brp = gru ? bb_rec : ba_rec;
    float*       st  = gru ? g_h    : g_g;
    const int    coff = gru * ND3;

    ull u2[64];
#pragma unroll
    for (int kp = 0; kp < 64; ++kp)
        u2[kp] = pk2(U[(size_t)(2 * kp) * ND3 + j], U[(size_t)(2 * kp + 1) * ND3 + j]);
    const float brec = brp[j];

    const int s = (j >> 7) & 1;
    const int d = j & 127;
    const bool gate_th = (j < 256);
    const bool pf_th   = (j >= 256);
    const int  pt      = j - 256;      // 0..127 prefetch id

    for (int pi = 0; pi < 2; ++pi) {
        const int pr = pi ? (147 - slot) : slot;
        if (pr >= 128) continue;       // slots 0..19 have no snake partner

        const int b_s0 = g_perm[2 * pr];
        const int b_s1 = g_perm[2 * pr + 1];
        const int len0 = lengths[b_s0];
        const int len1 = lengths[b_s1];
        const int maxlen = max(len0, len1);
        const int b_g   = s ? b_s1 : b_s0;
        const int len_g = s ? len1 : len0;
        float* stp = st + (size_t)b_g * TD + d;

        for (int idx = j; idx < 2 * DDIM; idx += 384) ((float*)hsm)[idx] = 0.f;

        // prime xsm[0] with step-0 rows (row len-1, always valid since len>=1)
        if (pf_th) {
#pragma unroll
            for (int i = 0; i < 3; ++i) {
                int p  = pt + 128 * i;        // float2 index over both samples
                int sp = (p >= 192) ? 1 : 0;
                int c2 = p - sp * 192;
                int bsp = sp ? b_s1 : b_s0;
                int lsp = sp ? len1 : len0;
                const float* gsrc = g_xpc + ((size_t)bsp * TSEQ + (lsp - 1)) * NC + coff + 2 * c2;
                cp8(sptr(&xsm[0][sp * 384 + 2 * c2]), gsrc);
            }
            CP_COMMIT();
            CP_WAIT0();
        }
        __syncthreads();

        for (int t = 0; t < maxlen; ++t) {
            const int buf  = t & 1;
            const bool more = (t + 1 < maxlen);
            // issue prefetch of step t+1 into buf^1 (flies during the FFMA phase)
            if (pf_th && more) {
#pragma unroll
                for (int i = 0; i < 3; ++i) {
                    int p  = pt + 128 * i;
                    int sp = (p >= 192) ? 1 : 0;
                    int c2 = p - sp * 192;
                    int bsp = sp ? b_s1 : b_s0;
                    int lsp = sp ? len1 : len0;
                    if (t + 1 < lsp) {
                        const float* gsrc = g_xpc + ((size_t)bsp * TSEQ + (lsp - 2 - t)) * NC + coff + 2 * c2;
                        cp8(sptr(&xsm[buf ^ 1][sp * 384 + 2 * c2]), gsrc);
                    }
                }
                CP_COMMIT();
            }

            // rp[s][j] = h[s] . U[:,j] + b_rec[j]
            ull acc0 = pk2(brec, 0.f);
            ull acc1 = pk2(brec, 0.f);
#pragma unroll
            for (int q = 0; q < 32; ++q) {
                ull u0 = u2[2 * q], u1 = u2[2 * q + 1];
                ulonglong2 h0 = *(const ulonglong2*)&hsm[0][4 * q];
                ulonglong2 h1 = *(const ulonglong2*)&hsm[1][4 * q];
                ffma2(acc0, u0, h0.x);
                ffma2(acc0, u1, h0.y);
                ffma2(acc1, u0, h1.x);
                ffma2(acc1, u1, h1.y);
            }
            { float2 f = upk2(acc0); rps[0][j] = f.x + f.y; }
            { float2 f = upk2(acc1); rps[1][j] = f.x + f.y; }

            if (pf_th) { if (more) { CP_WAIT1(); } else { CP_WAIT0(); } }
            __syncthreads();   // rps ready; xsm[buf] ready

            if (gate_th) {
                float h_old = hsm[s][d];
                float hn = h_old;
                if (t < len_g) {
                    float xz = xsm[buf][s * 384 + d];
                    float xr = xsm[buf][s * 384 + 128 + d];
                    float xh = xsm[buf][s * 384 + 256 + d];
                    float zg = sigm(xz + rps[s][d]);
                    float rg = sigm(xr + rps[s][128 + d]);
                    float hh = ftanh(xh + rg * rps[s][256 + d]);
                    hn = zg * h_old + (1.f - zg) * hh;
                }
                hsm[s][d] = hn;
                stp[0] = hn;
            }
            __syncthreads();   // hsm ready for next step's dots
            stp += DDIM;
        }
        // tail fill: t in [maxlen, T) carries the final state
        const int tail = TSEQ - maxlen;
        for (int idx = j; idx < tail * 256; idx += 384) {
            int dd = idx & 127;
            int ss = (idx >> 7) & 1;
            int tt = idx >> 8;
            int bb = ss ? b_s1 : b_s0;
            st[(size_t)bb * TD + (size_t)(maxlen + tt) * DDIM + dd] = hsm[ss][dd];
        }
        __syncthreads();
    }
}

// ============================================================================
// Kernel 3: fused attention epilogue. One 256-thread block per sample.
// Phase 2 splits K across two 128-thread halves (wb2[32] -> ~120 regs ->
// 2 blocks/SM, occ 25%); kh=1 writes partial sums to smem, kh=0 finishes
// (tanh, alpha*beta*x accumulate) and writes out. No atomics.
// ============================================================================
__global__ void __launch_bounds__(256, 2) k_attn(
    const float* __restrict__ x,
    const float* __restrict__ W_alpha, const float* __restrict__ b_alpha,
    const float* __restrict__ W_beta,  const float* __restrict__ b_beta,
    float* __restrict__ out)
{
    __shared__ float e_s[TSEQ];
    __shared__ float red[8];
    __shared__ float scal[2];
    __shared__ __align__(16) float hwin[8][DDIM];
    __shared__ float xwin[8][DDIM];
    __shared__ float psum[8][DDIM];

    const int b    = blockIdx.x;
    const int tid  = threadIdx.x;
    const int lane = tid & 31, w = tid >> 5;

    // ---- phase 1: e[t] = g[b][t] . W_alpha + b_alpha (warp per t, 8 warps) ----
    float4 wa = *(const float4*)&W_alpha[lane * 4];
    const float b_a = b_alpha[0];
    const float* gbase = g_g + (size_t)b * TD;
    for (int tt = 0; tt < 64; ++tt) {
        int t = tt * 8 + w;
        float4 gv = *(const float4*)&gbase[(size_t)t * DDIM + lane * 4];
        float sum = gv.x * wa.x + gv.y * wa.y + gv.z * wa.z + gv.w * wa.w;
#pragma unroll
        for (int o = 16; o > 0; o >>= 1) sum += __shfl_xor_sync(0xffffffffu, sum, o);
        if (lane == 0) e_s[t] = sum + b_a;
    }
    __syncthreads();

    // ---- softmax over t (unnormalized exp; divide once at the end) ----
    float m = -1e30f;
    for (int i = tid; i < TSEQ; i += 256) m = fmaxf(m, e_s[i]);
#pragma unroll
    for (int o = 16; o > 0; o >>= 1) m = fmaxf(m, __shfl_xor_sync(0xffffffffu, m, o));
    if (lane == 0) red[w] = m;
    __syncthreads();
    if (tid == 0) {
        float mm = red[0];
#pragma unroll
        for (int i = 1; i < 8; ++i) mm = fmaxf(mm, red[i]);
        scal[0] = mm;
    }
    __syncthreads();
    const float M = scal[0];
    float ss = 0.f;
    for (int i = tid; i < TSEQ; i += 256) { float p = __expf(e_s[i] - M); e_s[i] = p; ss += p; }
#pragma unroll
    for (int o = 16; o > 0; o >>= 1) ss += __shfl_xor_sync(0xffffffffu, ss, o);
    if (lane == 0) red[w] = ss;
    __syncthreads();
    if (tid == 0) {
        float t2 = 0.f;
#pragma unroll
        for (int i = 0; i < 8; ++i) t2 += red[i];
        scal[1] = t2;
    }
    __syncthreads();
    const float Sinv = 1.f / scal[1];

    // ---- phase 2: beta GEMV, K split across two 128-thread halves ----
    const int kh = tid >> 7;      // 0 or 1: K-half
    const int d  = tid & 127;

    ull wb2[32];
#pragma unroll
    for (int i = 0; i < 32; ++i) {
        int k0 = 64 * kh + 2 * i;
        wb2[i] = pk2(W_beta[(size_t)k0 * DDIM + d],
                     W_beta[(size_t)(k0 + 1) * DDIM + d]);
    }
    const float bbv = b_beta[d];
    const float* hbase = g_h + (size_t)b * TD;
    const float* xbase = x   + (size_t)b * TD;
    const float* hoff  = hbase + 64 * kh;   // this half's K window within each row
    float acc = 0.f;

    for (int tw = 0; tw < TSEQ; tw += 8) {
        __syncthreads();
        // cooperative window load (8 rows x 128 of h and x; 4 elems each per array)
#pragma unroll
        for (int l = 0; l < 4; ++l) {
            int idx = tid + l * 256;
            int tt = idx >> 7, k = idx & 127;
            hwin[tt][k] = hbase[(size_t)(tw + tt) * DDIM + k];
            xwin[tt][k] = xbase[(size_t)(tw + tt) * DDIM + k];
        }
        __syncthreads();
        float part[8];
#pragma unroll
        for (int tt = 0; tt < 8; ++tt) {
            // partial dot over this K-half, 2 interleaved chains
            ull a2a = 0ull, a2b = 0ull;
            const float* hrow = &hwin[tt][64 * kh];
#pragma unroll
            for (int q = 0; q < 16; q += 2) {
                ulonglong2 hva = *(const ulonglong2*)&hrow[4 * q];
                ulonglong2 hvb = *(const ulonglong2*)&hrow[4 * q + 4];
                ffma2(a2a, wb2[2 * q],     hva.x);
                ffma2(a2b, wb2[2 * q + 2], hvb.x);
                ffma2(a2a, wb2[2 * q + 1], hva.y);
                ffma2(a2b, wb2[2 * q + 3], hvb.y);
            }
            float2 fa = upk2(a2a);
            float2 fb = upk2(a2b);
            part[tt] = fa.x + fa.y + fb.x + fb.y;
        }
        if (kh == 1) {
#pragma unroll
            for (int tt = 0; tt < 8; ++tt) psum[tt][d] = part[tt];
        }
        __syncthreads();
        if (kh == 0) {
#pragma unroll
            for (int tt = 0; tt < 8; ++tt) {
                float beta = ftanh(part[tt] + psum[tt][d] + bbv);
                acc += e_s[tw + tt] * beta * xwin[tt][d];
            }
        }
    }
    if (kh == 0) out[(size_t)b * DDIM + d] = acc * Sinv;
    (void)hoff;
}

// ============================================================================
extern "C" void kernel_launch(void* const* d_in, const int* in_sizes, int n_in,
                              void* d_out, int out_size)
{
    const float* x       = (const float*)d_in[0];
    const int*   lengths = (const int*)  d_in[1];
    const float* Wa      = (const float*)d_in[2];
    const float* Ua      = (const float*)d_in[3];
    const float* ba_in   = (const float*)d_in[4];
    const float* ba_rec  = (const float*)d_in[5];
    const float* Wb      = (const float*)d_in[6];
    const float* Ub      = (const float*)d_in[7];
    const float* bb_in   = (const float*)d_in[8];
    const float* bb_rec  = (const float*)d_in[9];
    const float* W_alpha = (const float*)d_in[10];
    const float* b_alpha = (const float*)d_in[11];
    const float* W_beta  = (const float*)d_in[12];
    const float* b_beta  = (const float*)d_in[13];
    float* out = (float*)d_out;

    k_sort<<<1, BATCH>>>(lengths);
    k_xp  <<<dim3(2048, 12), 256>>>(x, lengths, Wa, ba_in, Wb, bb_in);
    k_gru <<<148, 384>>>(lengths, Ua, ba_rec, Ub, bb_rec);
    k_attn<<<256, 256>>>(x, W_alpha, b_alpha, W_beta, b_beta, out);
    (void)in_sizes; (void)n_in; (void)out_size;
}